// round 11
// baseline (speedup 1.0000x reference)
#include <cuda_runtime.h>
#include <math.h>

// SparseDimAttention, GB300 sm_103a — fully fused single kernel.
// 1 CTA per batch, 1 CTA/SM (128KB smem). Per CTA:
//   ph0: stage head weights (43KB) into smem + fold score projection
//   ph1: stream x[b] from DRAM (276 MB chip-wide, read ONCE) -> scores in smem
//   ph2: exact top-K via linear-bin select + softmax -> weights in smem
//   ph5: y[l] = sum_d w[d]*x[b,l,d], x[b] re-read from L2 (148 slices = 78MB < 126MB L2)
//   ph6: warp 0 computes head (LN -> W1+GELU -> W2) -> out[b]

constexpr int Ll = 33, Dd = 4096, Pp = 64, Kk = 512, Hh = 128, Bb = 512;
constexpr int BINS = 1024;

__device__ __forceinline__ unsigned int fkey(float f) {
    unsigned int u = __float_as_uint(f);
    return u ^ ((u & 0x80000000u) ? 0xFFFFFFFFu : 0x80000000u); // ascending monotonic
}

#define NTM 512
constexpr int CHM = Dd / NTM;      // 8
constexpr int BPTM = BINS / NTM;   // 2
constexpr int TREPM = BINS / NTM;  // 2
constexpr int SMEM_BYTES = 128 * 1024;  // forces 1 CTA/SM

__global__ void __launch_bounds__(NTM, 1) mega_kernel(
    const float* __restrict__ x, const float* __restrict__ Wp,
    const float* __restrict__ bp, const float* __restrict__ ws,
    const float* __restrict__ bsc, const float* __restrict__ gamma,
    const float* __restrict__ beta, const float* __restrict__ W1,
    const float* __restrict__ b1, const float* __restrict__ W2,
    const float* __restrict__ b2, float* __restrict__ out)
{
    extern __shared__ float dyn[];
    float* sc   = dyn;                       // [4096] scores -> weights
    int*   hist = (int*)(dyn + Dd);          // [1024]
    float* sW1  = dyn + Dd + BINS;           // [8192]
    float* sWp  = sW1 + Hh * Pp;             // [2112]
    float* sbp  = sWp + Pp * Ll;             // [64]
    float* sg   = sbp + Pp;                  // [64]
    float* sbe  = sg + Pp;                   // [64]
    float* sb1  = sbe + Pp;                  // [128]
    float* sW2  = sb1 + Hh;                  // [256]
    float* yv   = sW2 + 2 * Hh;              // [34]

    __shared__ float v[Ll];
    __shared__ float redmx[16], redmn[16], redf[16];
    __shared__ int   wsum_[16];
    __shared__ float zz[Pp];
    __shared__ float s_c, s_m, s_lo, s_scale, s_invZ;
    __shared__ int   s_thr, s_rem, s_cnt, s_T;

    const int b = blockIdx.x, tid = threadIdx.x;
    const int lane = tid & 31, wid = tid >> 5;

    // ---- phase 0: stage head weights + fold score projection ----
    for (int i = tid; i < Hh * Pp; i += NTM) sW1[i] = W1[i];
    for (int i = tid; i < Pp * Ll; i += NTM) sWp[i] = Wp[i];
    if (tid < 2 * Hh) sW2[tid] = W2[tid];
    if (tid < Pp) { sbp[tid] = bp[tid]; sg[tid] = gamma[tid]; sbe[tid] = beta[tid]; }
    if (tid < Hh) sb1[tid] = b1[tid];
    if (tid < Ll) {
        float a = 0.f;
        #pragma unroll
        for (int p = 0; p < Pp; ++p) a = fmaf(ws[p], Wp[p * Ll + tid], a);
        v[tid] = a;
    } else if (tid == Ll) {
        float a = bsc[0];
        #pragma unroll
        for (int p = 0; p < Pp; ++p) a = fmaf(ws[p], bp[p], a);
        s_c = a;
    }
    #pragma unroll
    for (int j = 0; j < BPTM; ++j) hist[j * NTM + tid] = 0;
    if (tid == 0) s_cnt = 0;
    __syncthreads();

    const float4* __restrict__ xb4 =
        reinterpret_cast<const float4*>(x) + (size_t)b * Ll * (Dd / 4);

    // ---- phase 1: stream x[b] from DRAM, scores into smem ----
    {
        const float cc = s_c;
        float4 a0 = make_float4(cc, cc, cc, cc);
        float4 a1 = make_float4(cc, cc, cc, cc);
        #pragma unroll 4
        for (int l = 0; l < Ll; ++l) {
            const float vl = v[l];
            const float4* row = xb4 + (size_t)l * (Dd / 4);
            float4 x0 = row[tid];
            float4 x1 = row[tid + NTM];
            a0.x = fmaf(vl, x0.x, a0.x); a0.y = fmaf(vl, x0.y, a0.y);
            a0.z = fmaf(vl, x0.z, a0.z); a0.w = fmaf(vl, x0.w, a0.w);
            a1.x = fmaf(vl, x1.x, a1.x); a1.y = fmaf(vl, x1.y, a1.y);
            a1.z = fmaf(vl, x1.z, a1.z); a1.w = fmaf(vl, x1.w, a1.w);
        }
        float4* sc4 = reinterpret_cast<float4*>(sc);
        sc4[tid] = a0;
        sc4[tid + NTM] = a1;
        float mx = fmaxf(fmaxf(a0.x, a0.y), fmaxf(a0.z, a0.w));
        mx = fmaxf(mx, fmaxf(fmaxf(a1.x, a1.y), fmaxf(a1.z, a1.w)));
        float mn = fminf(fminf(a0.x, a0.y), fminf(a0.z, a0.w));
        mn = fminf(mn, fminf(fminf(a1.x, a1.y), fminf(a1.z, a1.w)));
        #pragma unroll
        for (int o = 16; o > 0; o >>= 1) {
            mx = fmaxf(mx, __shfl_xor_sync(0xFFFFFFFFu, mx, o));
            mn = fminf(mn, __shfl_xor_sync(0xFFFFFFFFu, mn, o));
        }
        if (lane == 0) { redmx[wid] = mx; redmn[wid] = mn; }
    }
    __syncthreads();
    if (tid < 16) {
        float mx = redmx[tid], mn = redmn[tid];
        #pragma unroll
        for (int o = 8; o > 0; o >>= 1) {
            mx = fmaxf(mx, __shfl_xor_sync(0x0000FFFFu, mx, o));
            mn = fminf(mn, __shfl_xor_sync(0x0000FFFFu, mn, o));
        }
        if (tid == 0) {
            s_m = mx; s_lo = mn;
            const float r = mx - mn;
            s_scale = (r > 0.f) ? ((float)(BINS - 1) / r) : 0.f;
        }
    }
    __syncthreads();

    const float lo = s_lo, scale = s_scale, mm = s_m;
    // value-uniform histogram
    #pragma unroll
    for (int it = 0; it < CHM; ++it) {
        const float s = sc[it * NTM + tid];
        int bin = (int)((s - lo) * scale);
        bin = min(BINS - 1, max(0, bin));
        atomicAdd(&hist[bin], 1);
    }
    __syncthreads();

    // suffix scan: hist[i] = #elements with bin >= i
    {
        const int base = tid * BPTM;
        int c[BPTM];
        #pragma unroll
        for (int j = 0; j < BPTM; ++j) c[j] = hist[base + j];
        #pragma unroll
        for (int j = BPTM - 2; j >= 0; --j) c[j] += c[j + 1];
        int inc = c[0];
        #pragma unroll
        for (int o = 1; o < 32; o <<= 1) {
            int t = __shfl_up_sync(0xFFFFFFFFu, inc, o);
            if (lane >= o) inc += t;
        }
        if (lane == 31) wsum_[wid] = inc;
        __syncthreads();
        if (tid < 16) {
            int w = wsum_[tid];
            int iw = w;
            #pragma unroll
            for (int o = 1; o < 16; o <<= 1) {
                int t = __shfl_up_sync(0x0000FFFFu, iw, o);
                if (tid >= o) iw += t;
            }
            wsum_[tid] = iw - w;
            if (tid == 15) s_T = iw;
        }
        __syncthreads();
        const int S = s_T - (wsum_[wid] + inc);
        #pragma unroll
        for (int j = 0; j < BPTM; ++j) hist[base + j] = S + c[j];
    }
    __syncthreads();

    // threshold bin
    #pragma unroll
    for (int j = 0; j < BPTM; ++j) {
        const int i = tid * BPTM + j;
        const int hv = hist[i];
        const int nx = (i < BINS - 1) ? hist[i + 1] : 0;
        if (hv >= Kk && nx < Kk) { s_thr = i; s_rem = Kk - nx; }
    }
    __syncthreads();
    const int thr = s_thr, rem = s_rem;

    // tie list (reuse hist)
    #pragma unroll
    for (int it = 0; it < CHM; ++it) {
        const int d = it * NTM + tid;
        int bin = (int)((sc[d] - lo) * scale);
        bin = min(BINS - 1, max(0, bin));
        if (bin == thr) {
            int pos = atomicAdd(&s_cnt, 1);
            if (pos < BINS) hist[pos] = d;
        }
    }
    __syncthreads();
    const int cnt = s_cnt;
    const bool fast = (cnt <= BINS);

    // READ-ONLY: snapshot owner scores + rank ties by (key desc, idx asc)
    float sv[CHM];
    #pragma unroll
    for (int it = 0; it < CHM; ++it) sv[it] = sc[it * NTM + tid];

    float twl[TREPM]; int tdl[TREPM];
    float twf[CHM];
    if (fast) {
        #pragma unroll
        for (int rep = 0; rep < TREPM; ++rep) {
            const int i = rep * NTM + tid;
            twl[rep] = 0.f; tdl[rep] = -1;
            if (i < cnt) {
                const int d = hist[i];
                const float s = sc[d];
                const unsigned int ke = fkey(s);
                int rank = 0;
                for (int j2 = 0; j2 < cnt; ++j2) {
                    const int d2 = hist[j2];
                    const unsigned int k2 = fkey(sc[d2]);
                    rank += (k2 > ke) || (k2 == ke && d2 < d);
                }
                tdl[rep] = d;
                twl[rep] = (rank < rem) ? expf(s - mm) : 0.f;
            }
        }
    } else { // exact fallback (degenerate data only)
        #pragma unroll
        for (int it = 0; it < CHM; ++it) {
            const int d = it * NTM + tid;
            int bin = (int)((sv[it] - lo) * scale);
            bin = min(BINS - 1, max(0, bin));
            twf[it] = 0.f;
            if (bin == thr) {
                const unsigned int ke = fkey(sv[it]);
                int rank = 0;
                for (int d2 = 0; d2 < Dd; ++d2) {
                    const float s2 = sc[d2];
                    int b2i = (int)((s2 - lo) * scale);
                    b2i = min(BINS - 1, max(0, b2i));
                    if (b2i == thr) {
                        const unsigned int k2 = fkey(s2);
                        rank += (k2 > ke) || (k2 == ke && d2 < d);
                    }
                }
                twf[it] = (rank < rem) ? expf(sv[it] - mm) : 0.f;
            }
        }
    }
    __syncthreads();   // all sc reads done before writes

    // WRITE: disjoint writers, unnormalized weights into sc
    float zp = 0.f;
    #pragma unroll
    for (int it = 0; it < CHM; ++it) {
        const int d = it * NTM + tid;
        int bin = (int)((sv[it] - lo) * scale);
        bin = min(BINS - 1, max(0, bin));
        if (bin != thr) {
            const float w = (bin > thr) ? expf(sv[it] - mm) : 0.f;
            sc[d] = w; zp += w;
        } else if (!fast) {
            sc[d] = twf[it]; zp += twf[it];
        }
    }
    if (fast) {
        #pragma unroll
        for (int rep = 0; rep < TREPM; ++rep)
            if (tdl[rep] >= 0) { sc[tdl[rep]] = twl[rep]; zp += twl[rep]; }
    }
    #pragma unroll
    for (int o = 16; o > 0; o >>= 1) zp += __shfl_xor_sync(0xFFFFFFFFu, zp, o);
    if (lane == 0) redf[wid] = zp;
    __syncthreads();
    if (tid < 16) {
        zp = redf[tid];
        #pragma unroll
        for (int o = 8; o > 0; o >>= 1) zp += __shfl_xor_sync(0x0000FFFFu, zp, o);
        if (tid == 0) s_invZ = 1.f / zp;
    }
    __syncthreads();

    // ---- phase 5: y[l] = invZ * sum_d w[d]*x[b,l,d]  (x[b] re-read from L2) ----
    {
        const float invZ = s_invZ;
        const float4* sc4 = reinterpret_cast<const float4*>(sc);
        for (int l = wid; l < Ll; l += 16) {
            const float4* __restrict__ row = xb4 + (size_t)l * (Dd / 4);
            float a0 = 0.f, a1 = 0.f, a2 = 0.f, a3 = 0.f;
            #pragma unroll 4
            for (int i = lane; i < Dd / 4; i += 32) {
                float4 wv = sc4[i];
                float4 xv = row[i];
                a0 = fmaf(wv.x, xv.x, a0);
                a1 = fmaf(wv.y, xv.y, a1);
                a2 = fmaf(wv.z, xv.z, a2);
                a3 = fmaf(wv.w, xv.w, a3);
            }
            float acc = (a0 + a1) + (a2 + a3);
            #pragma unroll
            for (int o = 16; o > 0; o >>= 1) acc += __shfl_xor_sync(0xFFFFFFFFu, acc, o);
            if (lane == 0) yv[l] = acc * invZ;
        }
    }
    __syncthreads();

    // ---- phase 6: head on warp 0 ----
    if (wid == 0) {
        float z0 = sbp[lane], z1 = sbp[lane + 32];
        #pragma unroll
        for (int l = 0; l < Ll; ++l) {
            const float y = yv[l];
            z0 = fmaf(sWp[lane * Ll + l], y, z0);
            z1 = fmaf(sWp[(lane + 32) * Ll + l], y, z1);
        }
        float sum = z0 + z1;
        #pragma unroll
        for (int o = 16; o > 0; o >>= 1) sum += __shfl_xor_sync(0xFFFFFFFFu, sum, o);
        const float mu = sum * (1.f / 64.f);
        const float d0 = z0 - mu, d1 = z1 - mu;
        float sq = d0 * d0 + d1 * d1;
        #pragma unroll
        for (int o = 16; o > 0; o >>= 1) sq += __shfl_xor_sync(0xFFFFFFFFu, sq, o);
        const float rstd = rsqrtf(sq * (1.f / 64.f) + 1e-5f);
        zz[lane]      = d0 * rstd * sg[lane] + sbe[lane];
        zz[lane + 32] = d1 * rstd * sg[lane + 32] + sbe[lane + 32];
        __syncwarp();

        float a[4];
        #pragma unroll
        for (int k = 0; k < 4; ++k) {
            const int j = k * 32 + lane;
            float acc = sb1[j];
            #pragma unroll
            for (int p = 0; p < Pp; ++p) {
                const int pr = (p + lane) & (Pp - 1);
                acc = fmaf(sW1[j * Pp + pr], zz[pr], acc);
            }
            a[k] = 0.5f * acc * (1.f + erff(acc * 0.70710678118654752f)); // exact GELU
        }
        float o0 = 0.f, o1 = 0.f;
        #pragma unroll
        for (int k = 0; k < 4; ++k) {
            const int j = k * 32 + lane;
            o0 = fmaf(sW2[j], a[k], o0);
            o1 = fmaf(sW2[Hh + j], a[k], o1);
        }
        #pragma unroll
        for (int o = 16; o > 0; o >>= 1) {
            o0 += __shfl_xor_sync(0xFFFFFFFFu, o0, o);
            o1 += __shfl_xor_sync(0xFFFFFFFFu, o1, o);
        }
        if (lane == 0) {
            out[b * 2 + 0] = o0 + b2[0];
            out[b * 2 + 1] = o1 + b2[1];
        }
    }
}

extern "C" void kernel_launch(void* const* d_in, const int* in_sizes, int n_in,
                              void* d_out, int out_size) {
    const float* x     = (const float*)d_in[0];
    const float* Wp    = (const float*)d_in[1];
    const float* bp    = (const float*)d_in[2];
    const float* ws    = (const float*)d_in[3];
    const float* bsc   = (const float*)d_in[4];
    const float* gamma = (const float*)d_in[5];
    const float* beta  = (const float*)d_in[6];
    const float* W1    = (const float*)d_in[7];
    const float* b1    = (const float*)d_in[8];
    const float* W2    = (const float*)d_in[9];
    const float* b2    = (const float*)d_in[10];
    float* out = (float*)d_out;

    cudaFuncSetAttribute(mega_kernel, cudaFuncAttributeMaxDynamicSharedMemorySize, SMEM_BYTES);
    mega_kernel<<<Bb, NTM, SMEM_BYTES>>>(x, Wp, bp, ws, bsc, gamma, beta, W1, b1, W2, b2, out);
}